// round 1
// baseline (speedup 1.0000x reference)
#include <cuda_runtime.h>
#include <cuda_bf16.h>
#include <cstdint>

// Problem constants
#define Bsz 256
#define Tlen 512
#define Iin 5
#define HH 100
#define G4 400       // 4*H
#define NL 5
#define Oout 3
#define BT (Bsz*Tlen)   // 131072

// ---------------------------------------------------------------------------
// Scratch (device globals; allocation-free per harness rules)
// ---------------------------------------------------------------------------
__device__ float g_gates[(size_t)BT * G4];   // gate pre-activations for current layer (~210MB)
__device__ float g_hA[(size_t)BT * HH];      // hidden-seq ping  (~52MB)
__device__ float g_hB[(size_t)BT * HH];      // hidden-seq pong  (~52MB)

// ---------------------------------------------------------------------------
// Fast activations (MUFU-based; rel err ~1e-6, well under 1e-3 budget)
// ---------------------------------------------------------------------------
__device__ __forceinline__ float sigf(float x) {
    return __fdividef(1.0f, 1.0f + __expf(-x));
}
__device__ __forceinline__ float tanh_(float x) {
    return __fdividef(2.0f, 1.0f + __expf(-2.0f * x)) - 1.0f;
}

// ---------------------------------------------------------------------------
// Kernel 1a: layer-0 input projection. K=5, thread-per-output.
//   g_gates[m][n] = b0[n] + sum_k x[m][k] * Wih0[n][k]
// ---------------------------------------------------------------------------
__global__ void gemm_in0(const float* __restrict__ x,     // [BT, 5]
                         const float* __restrict__ Wih,   // [400, 5]
                         const float* __restrict__ bias)  // [400]
{
    int idx = blockIdx.x * blockDim.x + threadIdx.x;   // over BT*400
    int m = idx / G4;
    int n = idx - m * G4;
    const float* xr = x + (size_t)m * Iin;
    const float* wr = Wih + (size_t)n * Iin;
    float a = bias[n];
#pragma unroll
    for (int k = 0; k < Iin; k++) a += xr[k] * wr[k];
    g_gates[(size_t)idx] = a;
}

// ---------------------------------------------------------------------------
// Kernel 1b: layers 1..4 input projection. Register-tiled SGEMM.
//   C[BT,400] = X[BT,100] @ W[400,100]^T + bias
// Block tile 64x64, K-chunks of 20, 256 threads, 4x4 outputs/thread.
// ---------------------------------------------------------------------------
__global__ void gemm_in(int inSel,
                        const float* __restrict__ W,      // [400,100]
                        const float* __restrict__ bias)   // [400]
{
    const float* X = inSel ? g_hB : g_hA;
    __shared__ float Xs[20][65];   // k-major, padded (conflict-free)
    __shared__ float Ws[20][65];

    int tid = threadIdx.x;          // 256
    int tx = tid & 15, ty = tid >> 4;
    int m0 = blockIdx.x * 64;
    int n0 = blockIdx.y * 64;

    float acc[4][4] = {};

    for (int kc = 0; kc < 100; kc += 20) {
#pragma unroll
        for (int i = 0; i < 5; i++) {
            int idx = tid + i * 256;          // 0..1279
            int r  = idx / 20;                // tile row (m or n local)
            int kk = idx - r * 20;            // k local
            Xs[kk][r] = X[(size_t)(m0 + r) * 100 + kc + kk];
            int gn = n0 + r;
            Ws[kk][r] = (gn < G4) ? W[(size_t)gn * 100 + kc + kk] : 0.0f;
        }
        __syncthreads();
#pragma unroll
        for (int k = 0; k < 20; k++) {
            float xv[4], wv[4];
#pragma unroll
            for (int i = 0; i < 4; i++) xv[i] = Xs[k][ty * 4 + i];
#pragma unroll
            for (int j = 0; j < 4; j++) wv[j] = Ws[k][tx * 4 + j];
#pragma unroll
            for (int i = 0; i < 4; i++)
#pragma unroll
                for (int j = 0; j < 4; j++)
                    acc[i][j] += xv[i] * wv[j];
        }
        __syncthreads();
    }
#pragma unroll
    for (int i = 0; i < 4; i++) {
        size_t m = (size_t)(m0 + ty * 4 + i);
#pragma unroll
        for (int j = 0; j < 4; j++) {
            int n = n0 + tx * 4 + j;
            if (n < G4) g_gates[m * G4 + n] = acc[i][j] + bias[n];
        }
    }
}

// ---------------------------------------------------------------------------
// Kernel 2: sequential LSTM recurrence for one layer.
// Grid: 128 blocks, each owns 2 batch rows (batch fully independent).
// Threads 0..399: gate-thread g keeps W_hh[g][0..99] in REGISTERS (fully
// unrolled K loop). h state (both rows, packed float2) broadcast from smem.
// Threads 0..99 also do the per-unit activation/state update.
// Per-step cost model: ~1250 cyc FMA floor + ~250 cyc sync/activation.
// ---------------------------------------------------------------------------
__global__ __launch_bounds__(416, 1)
void lstm_rec(const float* __restrict__ W_hh,   // [400,100]
              int outSel)
{
    __shared__ __align__(16) float2 h2[HH];     // packed hidden state (row0,row1)
    __shared__ float gsh[2 * G4];               // staged gate pre-activations

    const int tid = threadIdx.x;
    const int b0 = blockIdx.x * 2;

    float w[HH];
    if (tid < G4) {
#pragma unroll
        for (int k = 0; k < HH; k++) w[k] = W_hh[(size_t)tid * HH + k];
    }
    if (tid < HH) h2[tid] = make_float2(0.0f, 0.0f);
    float c0 = 0.0f, c1 = 0.0f;

    const float* gp0 = g_gates + (size_t)b0 * Tlen * G4;
    const float* gp1 = g_gates + (size_t)(b0 + 1) * Tlen * G4;
    float* hout = outSel ? g_hB : g_hA;
    float* hs0 = hout + (size_t)b0 * Tlen * HH;
    float* hs1 = hout + (size_t)(b0 + 1) * Tlen * HH;

    // prefetch gate pre-activations for t=0
    float pg0 = 0.0f, pg1 = 0.0f;
    if (tid < G4) { pg0 = gp0[tid]; pg1 = gp1[tid]; }
    __syncthreads();

    for (int t = 0; t < Tlen; t++) {
        if (tid < G4) {
            float a0 = pg0, a1 = pg1;
            // prefetch next step's gates (hidden under the dot loop)
            int tn = (t + 1 < Tlen) ? (t + 1) : t;
            pg0 = gp0[(size_t)tn * G4 + tid];
            pg1 = gp1[(size_t)tn * G4 + tid];
#pragma unroll
            for (int k = 0; k < HH; k += 2) {
                float4 hv = *reinterpret_cast<const float4*>(&h2[k]);
                a0 += w[k] * hv.x;
                a1 += w[k] * hv.y;
                a0 += w[k + 1] * hv.z;
                a1 += w[k + 1] * hv.w;
            }
            gsh[tid] = a0;
            gsh[G4 + tid] = a1;
        }
        __syncthreads();
        if (tid < HH) {
            // PyTorch gate order: i, f, g, o
            float i0 = sigf(gsh[tid]);
            float f0 = sigf(gsh[tid + 100]);
            float g0 = tanh_(gsh[tid + 200]);
            float o0 = sigf(gsh[tid + 300]);
            c0 = f0 * c0 + i0 * g0;
            float h0 = o0 * tanh_(c0);

            float i1 = sigf(gsh[G4 + tid]);
            float f1 = sigf(gsh[G4 + tid + 100]);
            float g1 = tanh_(gsh[G4 + tid + 200]);
            float o1 = sigf(gsh[G4 + tid + 300]);
            c1 = f1 * c1 + i1 * g1;
            float h1 = o1 * tanh_(c1);

            h2[tid] = make_float2(h0, h1);
            hs0[(size_t)t * HH + tid] = h0;
            hs1[(size_t)t * HH + tid] = h1;
        }
        __syncthreads();
    }
}

// ---------------------------------------------------------------------------
// Kernel 3: BN (eval) + 3-layer MLP head on the last timestep.
// One block per batch row.
// ---------------------------------------------------------------------------
__global__ void head_kernel(int inSel,
                            const float* __restrict__ gamma,
                            const float* __restrict__ beta,
                            const float* __restrict__ rmean,
                            const float* __restrict__ rvar,
                            const float* __restrict__ W1, const float* __restrict__ b1,
                            const float* __restrict__ W2, const float* __restrict__ b2,
                            const float* __restrict__ W3, const float* __restrict__ b3,
                            float* __restrict__ out)
{
    __shared__ float xa[HH], ya[HH];
    const float* hseq = inSel ? g_hB : g_hA;
    int b = blockIdx.x, tid = threadIdx.x;

    if (tid < HH) {
        float v = hseq[((size_t)b * Tlen + (Tlen - 1)) * HH + tid];
        xa[tid] = (v - rmean[tid]) * rsqrtf(rvar[tid] + 1e-5f) * gamma[tid] + beta[tid];
    }
    __syncthreads();
    if (tid < HH) {
        float a = b1[tid];
#pragma unroll 4
        for (int k = 0; k < HH; k++) a += xa[k] * W1[(size_t)tid * HH + k];
        ya[tid] = fmaxf(a, 0.0f);
    }
    __syncthreads();
    if (tid < HH) {
        float a = b2[tid];
#pragma unroll 4
        for (int k = 0; k < HH; k++) a += ya[k] * W2[(size_t)tid * HH + k];
        xa[tid] = fmaxf(a, 0.0f);
    }
    __syncthreads();
    if (tid < Oout) {
        float a = b3[tid];
#pragma unroll 4
        for (int k = 0; k < HH; k++) a += xa[k] * W3[(size_t)tid * HH + k];
        out[(size_t)b * Oout + tid] = a;
    }
}

// ---------------------------------------------------------------------------
// kernel_launch: layer-serial pipeline, all graph-capturable launches.
// ---------------------------------------------------------------------------
extern "C" void kernel_launch(void* const* d_in, const int* in_sizes, int n_in,
                              void* d_out, int out_size)
{
    const float* x     = (const float*)d_in[0];
    const float* W_ih0 = (const float*)d_in[1];
    const float* W_hh0 = (const float*)d_in[2];
    const float* b0    = (const float*)d_in[3];
    const float* W_ih  = (const float*)d_in[4];   // [4,400,100]
    const float* W_hh  = (const float*)d_in[5];   // [4,400,100]
    const float* bb    = (const float*)d_in[6];   // [4,400]
    const float* gamma = (const float*)d_in[7];
    const float* beta  = (const float*)d_in[8];
    const float* rmean = (const float*)d_in[9];
    const float* rvar  = (const float*)d_in[10];
    const float* W1    = (const float*)d_in[11];
    const float* b1    = (const float*)d_in[12];
    const float* W2    = (const float*)d_in[13];
    const float* b2    = (const float*)d_in[14];
    const float* W3    = (const float*)d_in[15];
    const float* b3    = (const float*)d_in[16];
    float* out = (float*)d_out;

    // Layer 0: K=5 input projection + recurrence -> g_hA (sel 0)
    gemm_in0<<<(BT * G4) / 256, 256>>>(x, W_ih0, b0);
    lstm_rec<<<128, 416>>>(W_hh0, /*outSel=*/0);

    // Layers 1..4: tiled input GEMM + recurrence, ping-pong A/B
    dim3 ggrid(BT / 64, 7);   // 7*64 = 448 >= 400 (n guarded)
    for (int l = 0; l < NL - 1; l++) {
        int inSel  = (l % 2 == 0) ? 0 : 1;
        int outSel = 1 - inSel;
        gemm_in<<<ggrid, 256>>>(inSel, W_ih + (size_t)l * G4 * HH, bb + (size_t)l * G4);
        lstm_rec<<<128, 416>>>(W_hh + (size_t)l * G4 * HH, outSel);
    }

    // Final hidden sequence lives in g_hA (sel 0) after 4 ping-pongs.
    head_kernel<<<Bsz, 128>>>(0, gamma, beta, rmean, rvar,
                              W1, b1, W2, b2, W3, b3, out);
}

// round 2
// speedup vs baseline: 1.0756x; 1.0756x over previous
#include <cuda_runtime.h>
#include <cuda_bf16.h>
#include <cstdint>

// Problem constants
#define Bsz 256
#define Tlen 512
#define Iin 5
#define HH 100
#define G4 400       // 4*H
#define NL 5
#define Oout 3
#define BT (Bsz*Tlen)   // 131072

typedef unsigned long long ull;

// Packed fp32x2 FMA (Blackwell FFMA2) + pack/unpack helpers
#define FMA2(d, a, b, c) asm("fma.rn.f32x2 %0, %1, %2, %3;" : "=l"(d) : "l"(a), "l"(b), "l"(c))
#define PACK2(d, lo, hi) asm("mov.b64 %0, {%1, %2};" : "=l"(d) : "f"(lo), "f"(hi))
#define UNPACK2(lo, hi, v) asm("mov.b64 {%0, %1}, %2;" : "=f"(lo), "=f"(hi) : "l"(v))

// ---------------------------------------------------------------------------
// Scratch (device globals; allocation-free per harness rules)
// ---------------------------------------------------------------------------
__device__ float g_gates[(size_t)BT * G4];   // gate pre-activations (~210MB)
__device__ float g_hA[(size_t)BT * HH];      // hidden-seq ping
__device__ float g_hB[(size_t)BT * HH];      // hidden-seq pong

// ---------------------------------------------------------------------------
// Fast activations (MUFU-based; rel err ~1e-6)
// ---------------------------------------------------------------------------
__device__ __forceinline__ float sigf(float x) {
    return __fdividef(1.0f, 1.0f + __expf(-x));
}
__device__ __forceinline__ float tanh_(float x) {
    return __fdividef(2.0f, 1.0f + __expf(-2.0f * x)) - 1.0f;
}

// ---------------------------------------------------------------------------
// Kernel 1a: layer-0 input projection. K=5, thread-per-output.
// ---------------------------------------------------------------------------
__global__ void gemm_in0(const float* __restrict__ x,     // [BT, 5]
                         const float* __restrict__ Wih,   // [400, 5]
                         const float* __restrict__ bias)  // [400]
{
    int idx = blockIdx.x * blockDim.x + threadIdx.x;   // over BT*400
    int m = idx / G4;
    int n = idx - m * G4;
    const float* xr = x + (size_t)m * Iin;
    const float* wr = Wih + (size_t)n * Iin;
    float a = bias[n];
#pragma unroll
    for (int k = 0; k < Iin; k++) a += xr[k] * wr[k];
    g_gates[(size_t)idx] = a;
}

// ---------------------------------------------------------------------------
// Kernel 1b: layers 1..4 input projection, f32x2-packed SGEMM.
//   C[BT,400] = X[BT,100] @ W[400,100]^T + bias
// Tile 64(m) x 112(n), whole K=100 resident in smem (one barrier).
// 256 threads = 16(tx for n) x 16(ty for m); each thread: 4 m-rows
// (ty+16i) x 7 n-rows (tx+16j), accumulators packed over (even k, odd k).
// Per k-pair: 4 broadcast X loads + 7 conflict-free W loads + 28 FFMA2.
// ---------------------------------------------------------------------------
#define GM 64
#define GNJ 7
#define GN (16*GNJ)   // 112
#define KP 102        // padded k stride (gcd(102,32)=2 -> conflict-free rows)
#define GEMM_SMEM ((GM + GN) * KP * 4)

__global__ __launch_bounds__(256)
void gemm_in(int inSel,
             const float* __restrict__ W,      // [400,100]
             const float* __restrict__ bias)   // [400]
{
    extern __shared__ float sm[];
    float* Xs = sm;                // [64][102]
    float* Ws = sm + GM * KP;      // [112][102]

    const float* X = inSel ? g_hB : g_hA;
    int tid = threadIdx.x;
    int tx = tid & 15;
    int ty = (tid >> 4) & 15;
    size_t m0 = (size_t)blockIdx.x * GM;
    int n0 = blockIdx.y * GN;

    // Load X tile (direct copy, k contiguous both sides)
    {
        const float2* Xg = (const float2*)(X + m0 * 100);
        for (int idx = tid; idx < GM * 50; idx += 256) {
            int r = idx / 50, c = idx - r * 50;
            float2 v = Xg[(size_t)r * 50 + c];
            *(float2*)&Xs[r * KP + 2 * c] = v;
        }
        const float2* Wg = (const float2*)W;
        for (int idx = tid; idx < GN * 50; idx += 256) {
            int r = idx / 50, c = idx - r * 50;
            int gn = n0 + r;
            float2 v = (gn < G4) ? Wg[(size_t)gn * 50 + c] : make_float2(0.f, 0.f);
            *(float2*)&Ws[r * KP + 2 * c] = v;
        }
    }
    __syncthreads();

    ull acc[4][GNJ];
#pragma unroll
    for (int i = 0; i < 4; i++)
#pragma unroll
        for (int j = 0; j < GNJ; j++) PACK2(acc[i][j], 0.f, 0.f);

    const ull* xrow[4];
#pragma unroll
    for (int i = 0; i < 4; i++) xrow[i] = (const ull*)&Xs[(ty + 16 * i) * KP];
    const ull* wrow[GNJ];
#pragma unroll
    for (int j = 0; j < GNJ; j++) wrow[j] = (const ull*)&Ws[(tx + 16 * j) * KP];

#pragma unroll 5
    for (int k = 0; k < 50; k++) {
        ull dx[4], dw[GNJ];
#pragma unroll
        for (int i = 0; i < 4; i++) dx[i] = xrow[i][k];
#pragma unroll
        for (int j = 0; j < GNJ; j++) dw[j] = wrow[j][k];
#pragma unroll
        for (int i = 0; i < 4; i++)
#pragma unroll
            for (int j = 0; j < GNJ; j++)
                FMA2(acc[i][j], dx[i], dw[j], acc[i][j]);
    }

    // Epilogue: reduce lane pairs, add bias, store
#pragma unroll
    for (int i = 0; i < 4; i++) {
        size_t m = m0 + ty + 16 * i;
#pragma unroll
        for (int j = 0; j < GNJ; j++) {
            int n = n0 + tx + 16 * j;
            if (n < G4) {
                float lo, hi;
                UNPACK2(lo, hi, acc[i][j]);
                g_gates[m * G4 + n] = lo + hi + bias[n];
            }
        }
    }
}

// ---------------------------------------------------------------------------
// Kernel 2: sequential LSTM recurrence, f32x2-packed.
// 128 blocks x 2 batch rows. Gate-thread g keeps W_hh[g] as 50 packed
// (k,k+1) pairs in registers; per step 100 FFMA2 across 4 accumulator
// chains. Activation split across 200 threads (row0: tid<100, row1:
// 100<=tid<200), each owning its cell state c.
// ---------------------------------------------------------------------------
__global__ __launch_bounds__(416, 1)
void lstm_rec(const float* __restrict__ W_hh,   // [400,100]
              int outSel, int storeAll)
{
    __shared__ __align__(16) float h0s[HH];
    __shared__ __align__(16) float h1s[HH];
    __shared__ float gsh[2 * G4];

    const int tid = threadIdx.x;
    const int b0 = blockIdx.x * 2;

    ull w2[50];
    if (tid < G4) {
        const float4* wr = (const float4*)(W_hh + (size_t)tid * HH);
#pragma unroll
        for (int j = 0; j < 25; j++) {
            float4 v = wr[j];
            PACK2(w2[2 * j],     v.x, v.y);
            PACK2(w2[2 * j + 1], v.z, v.w);
        }
    }
    if (tid < HH) h0s[tid] = 0.f;
    else if (tid < 2 * HH) h1s[tid - HH] = 0.f;
    float c = 0.f;   // per-unit cell state (valid for tid < 200)

    const float* gp0 = g_gates + (size_t)b0 * Tlen * G4;
    const float* gp1 = gp0 + (size_t)Tlen * G4;
    float* hout = outSel ? g_hB : g_hA;
    float* hs0 = hout + (size_t)b0 * Tlen * HH;
    float* hs1 = hs0 + (size_t)Tlen * HH;

    float pg0 = 0.f, pg1 = 0.f;
    if (tid < G4) { pg0 = gp0[tid]; pg1 = gp1[tid]; }
    __syncthreads();

    for (int t = 0; t < Tlen; t++) {
        if (tid < G4) {
            ull a00, a01, a10, a11;
            PACK2(a00, pg0, 0.f); PACK2(a01, 0.f, 0.f);
            PACK2(a10, pg1, 0.f); PACK2(a11, 0.f, 0.f);
            // prefetch next step's gate pre-activations under the dot
            int tn = (t + 1 < Tlen) ? (t + 1) : t;
            pg0 = gp0[(size_t)tn * G4 + tid];
            pg1 = gp1[(size_t)tn * G4 + tid];

            const ulonglong2* h0v = (const ulonglong2*)h0s;
            const ulonglong2* h1v = (const ulonglong2*)h1s;
#pragma unroll
            for (int j = 0; j < 25; j++) {
                ulonglong2 p0 = h0v[j];   // h row0, k = 4j..4j+3 (two pairs)
                ulonglong2 p1 = h1v[j];
                FMA2(a00, w2[2 * j],     p0.x, a00);
                FMA2(a01, w2[2 * j + 1], p0.y, a01);
                FMA2(a10, w2[2 * j],     p1.x, a10);
                FMA2(a11, w2[2 * j + 1], p1.y, a11);
            }
            float x0, y0, x1, y1;
            UNPACK2(x0, y0, a00); UNPACK2(x1, y1, a01);
            gsh[tid] = (x0 + y0) + (x1 + y1);
            UNPACK2(x0, y0, a10); UNPACK2(x1, y1, a11);
            gsh[G4 + tid] = (x0 + y0) + (x1 + y1);
        }
        __syncthreads();
        if (tid < 2 * HH) {
            int u = (tid < HH) ? tid : (tid - HH);
            const float* gs = (tid < HH) ? gsh : (gsh + G4);
            // PyTorch gate order: i, f, g, o
            float iv = sigf(gs[u]);
            float fv = sigf(gs[u + 100]);
            float gv = tanh_(gs[u + 200]);
            float ov = sigf(gs[u + 300]);
            c = fv * c + iv * gv;
            float hv = ov * tanh_(c);
            if (tid < HH) h0s[u] = hv; else h1s[u] = hv;
            if (storeAll || t == Tlen - 1) {
                float* dst = (tid < HH) ? hs0 : hs1;
                dst[(size_t)t * HH + u] = hv;
            }
        }
        __syncthreads();
    }
}

// ---------------------------------------------------------------------------
// Kernel 3: BN (eval) + 3-layer MLP head on the last timestep.
// ---------------------------------------------------------------------------
__global__ void head_kernel(int inSel,
                            const float* __restrict__ gamma,
                            const float* __restrict__ beta,
                            const float* __restrict__ rmean,
                            const float* __restrict__ rvar,
                            const float* __restrict__ W1, const float* __restrict__ b1,
                            const float* __restrict__ W2, const float* __restrict__ b2,
                            const float* __restrict__ W3, const float* __restrict__ b3,
                            float* __restrict__ out)
{
    __shared__ float xa[HH], ya[HH];
    const float* hseq = inSel ? g_hB : g_hA;
    int b = blockIdx.x, tid = threadIdx.x;

    if (tid < HH) {
        float v = hseq[((size_t)b * Tlen + (Tlen - 1)) * HH + tid];
        xa[tid] = (v - rmean[tid]) * rsqrtf(rvar[tid] + 1e-5f) * gamma[tid] + beta[tid];
    }
    __syncthreads();
    if (tid < HH) {
        float a = b1[tid];
#pragma unroll 4
        for (int k = 0; k < HH; k++) a += xa[k] * W1[(size_t)tid * HH + k];
        ya[tid] = fmaxf(a, 0.0f);
    }
    __syncthreads();
    if (tid < HH) {
        float a = b2[tid];
#pragma unroll 4
        for (int k = 0; k < HH; k++) a += ya[k] * W2[(size_t)tid * HH + k];
        xa[tid] = fmaxf(a, 0.0f);
    }
    __syncthreads();
    if (tid < Oout) {
        float a = b3[tid];
#pragma unroll 4
        for (int k = 0; k < HH; k++) a += xa[k] * W3[(size_t)tid * HH + k];
        out[(size_t)b * Oout + tid] = a;
    }
}

// ---------------------------------------------------------------------------
// kernel_launch: layer-serial pipeline, all graph-capturable launches.
// ---------------------------------------------------------------------------
extern "C" void kernel_launch(void* const* d_in, const int* in_sizes, int n_in,
                              void* d_out, int out_size)
{
    const float* x     = (const float*)d_in[0];
    const float* W_ih0 = (const float*)d_in[1];
    const float* W_hh0 = (const float*)d_in[2];
    const float* b0    = (const float*)d_in[3];
    const float* W_ih  = (const float*)d_in[4];   // [4,400,100]
    const float* W_hh  = (const float*)d_in[5];   // [4,400,100]
    const float* bb    = (const float*)d_in[6];   // [4,400]
    const float* gamma = (const float*)d_in[7];
    const float* beta  = (const float*)d_in[8];
    const float* rmean = (const float*)d_in[9];
    const float* rvar  = (const float*)d_in[10];
    const float* W1    = (const float*)d_in[11];
    const float* b1    = (const float*)d_in[12];
    const float* W2    = (const float*)d_in[13];
    const float* b2    = (const float*)d_in[14];
    const float* W3    = (const float*)d_in[15];
    const float* b3    = (const float*)d_in[16];
    float* out = (float*)d_out;

    cudaFuncSetAttribute((const void*)gemm_in,
                         cudaFuncAttributeMaxDynamicSharedMemorySize, GEMM_SMEM);

    // Layer 0: K=5 input projection + recurrence -> g_hA (sel 0)
    gemm_in0<<<(BT * G4) / 256, 256>>>(x, W_ih0, b0);
    lstm_rec<<<128, 416>>>(W_hh0, /*outSel=*/0, /*storeAll=*/1);

    // Layers 1..4: input GEMM + recurrence, ping-pong A/B
    dim3 ggrid(BT / GM, 4);   // 4*112 = 448 >= 400 (n guarded)
    for (int l = 0; l < NL - 1; l++) {
        int inSel  = (l % 2 == 0) ? 0 : 1;
        int outSel = 1 - inSel;
        gemm_in<<<ggrid, 256, GEMM_SMEM>>>(inSel, W_ih + (size_t)l * G4 * HH,
                                           bb + (size_t)l * G4);
        lstm_rec<<<128, 416>>>(W_hh + (size_t)l * G4 * HH, outSel,
                               (l == NL - 2) ? 0 : 1);
    }

    // Final hidden sequence lives in g_hA (sel 0).
    head_kernel<<<Bsz, 128>>>(0, gamma, beta, rmean, rvar,
                              W1, b1, W2, b2, W3, b3, out);
}